// round 1
// baseline (speedup 1.0000x reference)
#include <cuda_runtime.h>
#include <cstdint>

#define NN   50000
#define ECNT 800000

// ---------------- scratch (device globals; no allocation allowed) ----------
__device__ float g_deg [NN];
__device__ float g_dinv[NN];
__device__ float g_h1[(size_t)NN * 256];
__device__ float g_a1[(size_t)NN * 256];
__device__ float g_h2[(size_t)NN * 64];
__device__ float g_z [(size_t)NN * 64];
__device__ float g_d [(size_t)NN * 256];

// ---------------- degree / normalization ----------------------------------
__global__ void k_deg_init() {
    int i = blockIdx.x * 256 + threadIdx.x;
    if (i < NN) g_deg[i] = 1.0f;           // self-loop contributes 1
}
__global__ void k_deg_count(const int* __restrict__ dst) {
    int e = blockIdx.x * 256 + threadIdx.x;
    if (e < ECNT) atomicAdd(&g_deg[dst[e]], 1.0f);
}
__global__ void k_dinv() {
    int i = blockIdx.x * 256 + threadIdx.x;
    if (i < NN) g_dinv[i] = rsqrtf(g_deg[i]);   // deg >= 1 always
}

// ---------------- tiled fp32 GEMM: C = op(A[MxK]) @ B[KxN] (+bias)(relu) ---
// TM=128, TN=64, TK=16, 256 threads, 8x4 micro-tile per thread.
template<bool RELU_A, bool BIAS, bool RELU_OUT>
__global__ void k_gemm(const float* __restrict__ A, const float* __restrict__ B,
                       const float* __restrict__ bias, float* __restrict__ C,
                       int M, int N, int K)
{
    const int TM = 128, TN = 64, TK = 16;
    __shared__ float As[TK][TM];   // k-major for vectorized compute reads
    __shared__ float Bs[TK][TN];

    int bm = blockIdx.y * TM;
    int bn = blockIdx.x * TN;
    int tid = threadIdx.x;           // 0..255
    int tx = tid & 15;               // n-dir
    int ty = tid >> 4;               // m-dir

    float acc[8][4];
#pragma unroll
    for (int i = 0; i < 8; i++)
#pragma unroll
        for (int j = 0; j < 4; j++) acc[i][j] = 0.0f;

    for (int k0 = 0; k0 < K; k0 += TK) {
        // ---- load A tile 128x16 (512 float4, 2 per thread), transpose to k-major
#pragma unroll
        for (int i = 0; i < 2; i++) {
            int f  = tid + i * 256;
            int ar = f >> 2;                 // 0..127 (row in tile)
            int kq = f & 3;                  // which k-quad
            int row = bm + ar;
            float4 v = make_float4(0.f, 0.f, 0.f, 0.f);
            if (row < M)
                v = *(const float4*)&A[(size_t)row * K + k0 + kq * 4];
            if (RELU_A) {
                v.x = fmaxf(v.x, 0.f); v.y = fmaxf(v.y, 0.f);
                v.z = fmaxf(v.z, 0.f); v.w = fmaxf(v.w, 0.f);
            }
            As[kq * 4 + 0][ar] = v.x;
            As[kq * 4 + 1][ar] = v.y;
            As[kq * 4 + 2][ar] = v.z;
            As[kq * 4 + 3][ar] = v.w;
        }
        // ---- load B tile 16x64 (256 float4, 1 per thread)
        {
            int bk = tid >> 4;               // 0..15
            int bc = (tid & 15) * 4;         // 0..60
            *(float4*)&Bs[bk][bc] =
                *(const float4*)&B[(size_t)(k0 + bk) * N + bn + bc];
        }
        __syncthreads();

#pragma unroll
        for (int k = 0; k < TK; k++) {
            float4 a0 = *(const float4*)&As[k][ty * 8];
            float4 a1 = *(const float4*)&As[k][ty * 8 + 4];
            float4 b  = *(const float4*)&Bs[k][tx * 4];
            float av[8] = {a0.x, a0.y, a0.z, a0.w, a1.x, a1.y, a1.z, a1.w};
            float bv[4] = {b.x, b.y, b.z, b.w};
#pragma unroll
            for (int i = 0; i < 8; i++)
#pragma unroll
                for (int j = 0; j < 4; j++)
                    acc[i][j] = fmaf(av[i], bv[j], acc[i][j]);
        }
        __syncthreads();
    }

    float4 bv = make_float4(0.f, 0.f, 0.f, 0.f);
    if (BIAS) bv = *(const float4*)&bias[bn + tx * 4];
#pragma unroll
    for (int i = 0; i < 8; i++) {
        int row = bm + ty * 8 + i;
        if (row >= M) continue;
        float4 o;
        o.x = acc[i][0] + bv.x;
        o.y = acc[i][1] + bv.y;
        o.z = acc[i][2] + bv.z;
        o.w = acc[i][3] + bv.w;
        if (RELU_OUT) {
            o.x = fmaxf(o.x, 0.f); o.y = fmaxf(o.y, 0.f);
            o.z = fmaxf(o.z, 0.f); o.w = fmaxf(o.w, 0.f);
        }
        *(float4*)&C[(size_t)row * N + bn + tx * 4] = o;
    }
}

// ---------------- init aggregation: agg[i] = h[i]*dinv[i]^2 + b ------------
template<int C>
__global__ void k_init_agg(const float* __restrict__ h,
                           const float* __restrict__ bias,
                           float* __restrict__ agg)
{
    const int V = C / 4;
    int idx = blockIdx.x * 256 + threadIdx.x;
    if (idx >= NN * V) return;
    int node = idx / V;
    int v    = idx % V;
    float di = g_dinv[node];
    float s  = di * di;
    float4 hv = ((const float4*)h)[(size_t)node * V + v];
    float4 bv = ((const float4*)bias)[v];
    float4 o;
    o.x = fmaf(hv.x, s, bv.x);
    o.y = fmaf(hv.y, s, bv.y);
    o.z = fmaf(hv.z, s, bv.z);
    o.w = fmaf(hv.w, s, bv.w);
    ((float4*)agg)[(size_t)node * V + v] = o;
}

// ---------------- edge scatter: agg[dst] += h[src] * dinv[src]*dinv[dst] ---
// LPE lanes cooperate on one edge; vector reductions via red.global.add.v4.f32
template<int C, int LPE>
__global__ void k_scatter(const int* __restrict__ src, const int* __restrict__ dst,
                          const float* __restrict__ h, float* __restrict__ agg)
{
    const int V = C / 4;
    int t   = blockIdx.x * 256 + threadIdx.x;
    int e   = t / LPE;
    int sub = t % LPE;
    if (e >= ECNT) return;
    int s = src[e];
    int d = dst[e];
    float norm = g_dinv[s] * g_dinv[d];
    const float4* hp = (const float4*)h   + (size_t)s * V;
    float4*       ap = (float4*)agg       + (size_t)d * V;
#pragma unroll
    for (int v = sub; v < V; v += LPE) {
        float4 hv = hp[v];
        float mx = hv.x * norm, my = hv.y * norm, mz = hv.z * norm, mw = hv.w * norm;
        asm volatile("red.global.add.v4.f32 [%0], {%1, %2, %3, %4};"
                     :: "l"(ap + v), "f"(mx), "f"(my), "f"(mz), "f"(mw)
                     : "memory");
    }
}

// ---------------- launch ---------------------------------------------------
extern "C" void kernel_launch(void* const* d_in, const int* in_sizes, int n_in,
                              void* d_out, int out_size)
{
    const float* x   = (const float*)d_in[0];
    const int*   ei  = (const int*)  d_in[1];   // [2, E] int32, row-major
    const float* W1  = (const float*)d_in[2];
    const float* b1  = (const float*)d_in[3];
    const float* W2  = (const float*)d_in[4];
    const float* b2  = (const float*)d_in[5];
    const float* Wd1 = (const float*)d_in[6];
    const float* bd1 = (const float*)d_in[7];
    const float* Wd2 = (const float*)d_in[8];
    const float* bd2 = (const float*)d_in[9];
    float* out = (float*)d_out;

    const int* srcp = ei;
    const int* dstp = ei + ECNT;

    float *p_h1, *p_a1, *p_h2, *p_z, *p_d;
    cudaGetSymbolAddress((void**)&p_h1, g_h1);
    cudaGetSymbolAddress((void**)&p_a1, g_a1);
    cudaGetSymbolAddress((void**)&p_h2, g_h2);
    cudaGetSymbolAddress((void**)&p_z,  g_z);
    cudaGetSymbolAddress((void**)&p_d,  g_d);

    // --- degree + normalization
    k_deg_init <<<(NN   + 255) / 256, 256>>>();
    k_deg_count<<<(ECNT + 255) / 256, 256>>>(dstp);
    k_dinv     <<<(NN   + 255) / 256, 256>>>();

    const int MB = (NN + 127) / 128;   // 391 row-blocks

    // --- layer 1: h1 = x @ W1 ; a1 = scatter(h1) + b1
    k_gemm<false,false,false><<<dim3(256/64, MB), 256>>>(x, W1, nullptr, p_h1, NN, 256, 128);
    k_init_agg<256><<<(NN * 64 + 255) / 256, 256>>>(p_h1, b1, p_a1);
    k_scatter<256,32><<<(ECNT * 32) / 256, 256>>>(srcp, dstp, p_h1, p_a1);

    // --- layer 2: h2 = relu(a1) @ W2 ; z = scatter(h2) + b2
    k_gemm<true,false,false><<<dim3(64/64, MB), 256>>>(p_a1, W2, nullptr, p_h2, NN, 64, 256);
    k_init_agg<64><<<(NN * 16 + 255) / 256, 256>>>(p_h2, b2, p_z);
    k_scatter<64,16><<<(ECNT * 16) / 256, 256>>>(srcp, dstp, p_h2, p_z);

    // --- decoder: d = relu(z @ Wd1 + bd1) ; out = d @ Wd2 + bd2
    k_gemm<false,true,true ><<<dim3(256/64, MB), 256>>>(p_z, Wd1, bd1, p_d, NN, 256, 64);
    k_gemm<false,true,false><<<dim3(128/64, MB), 256>>>(p_d, Wd2, bd2, out, NN, 128, 256);
}

// round 2
// speedup vs baseline: 1.1431x; 1.1431x over previous
#include <cuda_runtime.h>
#include <cstdint>

#define NN   50000
#define ECNT 800000

// ---------------- scratch (device globals; no allocation allowed) ----------
__device__ float g_deg [NN];
__device__ float g_dinv[NN];
__device__ float g_aggx[(size_t)NN * 128];   // scatter(x) result
__device__ float g_h1r [(size_t)NN * 256];   // relu(a1)
__device__ float g_h2  [(size_t)NN * 64];
__device__ float g_z   [(size_t)NN * 64];
__device__ float g_d   [(size_t)NN * 256];

// ---------------- degree / normalization ----------------------------------
__global__ void k_deg_init() {
    int i = blockIdx.x * 256 + threadIdx.x;
    if (i < NN) g_deg[i] = 1.0f;           // self-loop contributes 1
}
__global__ void k_deg_count(const int* __restrict__ dst) {
    int e = blockIdx.x * 256 + threadIdx.x;
    if (e < ECNT) atomicAdd(&g_deg[dst[e]], 1.0f);
}
__global__ void k_dinv() {
    int i = blockIdx.x * 256 + threadIdx.x;
    if (i < NN) g_dinv[i] = rsqrtf(g_deg[i]);   // deg >= 1 always
}

// ---------------- tiled fp32 GEMM: C = A[MxK] @ B[KxN] (+bias)(relu) -------
// TM=128, TN=64, TK=16, 256 threads, 8x4 micro-tile per thread.
template<bool BIAS, bool RELU_OUT>
__global__ void k_gemm(const float* __restrict__ A, const float* __restrict__ B,
                       const float* __restrict__ bias, float* __restrict__ C,
                       int M, int N, int K)
{
    const int TM = 128, TN = 64, TK = 16;
    __shared__ float As[TK][TM];   // k-major for vectorized compute reads
    __shared__ float Bs[TK][TN];

    int bm = blockIdx.y * TM;
    int bn = blockIdx.x * TN;
    int tid = threadIdx.x;           // 0..255
    int tx = tid & 15;               // n-dir
    int ty = tid >> 4;               // m-dir

    float acc[8][4];
#pragma unroll
    for (int i = 0; i < 8; i++)
#pragma unroll
        for (int j = 0; j < 4; j++) acc[i][j] = 0.0f;

    for (int k0 = 0; k0 < K; k0 += TK) {
        // ---- load A tile 128x16 (512 float4, 2 per thread), transpose to k-major
#pragma unroll
        for (int i = 0; i < 2; i++) {
            int f  = tid + i * 256;
            int ar = f >> 2;                 // 0..127 (row in tile)
            int kq = f & 3;                  // which k-quad
            int row = bm + ar;
            float4 v = make_float4(0.f, 0.f, 0.f, 0.f);
            if (row < M)
                v = *(const float4*)&A[(size_t)row * K + k0 + kq * 4];
            As[kq * 4 + 0][ar] = v.x;
            As[kq * 4 + 1][ar] = v.y;
            As[kq * 4 + 2][ar] = v.z;
            As[kq * 4 + 3][ar] = v.w;
        }
        // ---- load B tile 16x64 (256 float4, 1 per thread)
        {
            int bk = tid >> 4;               // 0..15
            int bc = (tid & 15) * 4;         // 0..60
            *(float4*)&Bs[bk][bc] =
                *(const float4*)&B[(size_t)(k0 + bk) * N + bn + bc];
        }
        __syncthreads();

#pragma unroll
        for (int k = 0; k < TK; k++) {
            float4 a0 = *(const float4*)&As[k][ty * 8];
            float4 a1 = *(const float4*)&As[k][ty * 8 + 4];
            float4 b  = *(const float4*)&Bs[k][tx * 4];
            float av[8] = {a0.x, a0.y, a0.z, a0.w, a1.x, a1.y, a1.z, a1.w};
            float bv[4] = {b.x, b.y, b.z, b.w};
#pragma unroll
            for (int i = 0; i < 8; i++)
#pragma unroll
                for (int j = 0; j < 4; j++)
                    acc[i][j] = fmaf(av[i], bv[j], acc[i][j]);
        }
        __syncthreads();
    }

    float4 bv = make_float4(0.f, 0.f, 0.f, 0.f);
    if (BIAS) bv = *(const float4*)&bias[bn + tx * 4];
#pragma unroll
    for (int i = 0; i < 8; i++) {
        int row = bm + ty * 8 + i;
        if (row >= M) continue;
        float4 o;
        o.x = acc[i][0] + bv.x;
        o.y = acc[i][1] + bv.y;
        o.z = acc[i][2] + bv.z;
        o.w = acc[i][3] + bv.w;
        if (RELU_OUT) {
            o.x = fmaxf(o.x, 0.f); o.y = fmaxf(o.y, 0.f);
            o.z = fmaxf(o.z, 0.f); o.w = fmaxf(o.w, 0.f);
        }
        *(float4*)&C[(size_t)row * N + bn + tx * 4] = o;
    }
}

// ---------------- init aggregation: agg[i] = h[i]*dinv[i]^2 (+ b) ----------
template<int C, bool BIAS>
__global__ void k_init_agg(const float* __restrict__ h,
                           const float* __restrict__ bias,
                           float* __restrict__ agg)
{
    const int V = C / 4;
    int idx = blockIdx.x * 256 + threadIdx.x;
    if (idx >= NN * V) return;
    int node = idx / V;
    int v    = idx % V;
    float di = g_dinv[node];
    float s  = di * di;
    float4 hv = ((const float4*)h)[(size_t)node * V + v];
    float4 o;
    if (BIAS) {
        float4 bv = ((const float4*)bias)[v];
        o.x = fmaf(hv.x, s, bv.x);
        o.y = fmaf(hv.y, s, bv.y);
        o.z = fmaf(hv.z, s, bv.z);
        o.w = fmaf(hv.w, s, bv.w);
    } else {
        o.x = hv.x * s; o.y = hv.y * s; o.z = hv.z * s; o.w = hv.w * s;
    }
    ((float4*)agg)[(size_t)node * V + v] = o;
}

// ---------------- edge scatter: agg[dst] += h[src] * dinv[src]*dinv[dst] ---
// LPE lanes cooperate on one edge; vector reductions via red.global.add.v4.f32
template<int C, int LPE>
__global__ void k_scatter(const int* __restrict__ src, const int* __restrict__ dst,
                          const float* __restrict__ h, float* __restrict__ agg)
{
    const int V = C / 4;
    int t   = blockIdx.x * 256 + threadIdx.x;
    int e   = t / LPE;
    int sub = t % LPE;
    if (e >= ECNT) return;
    int s = src[e];
    int d = dst[e];
    float norm = g_dinv[s] * g_dinv[d];
    const float4* hp = (const float4*)h   + (size_t)s * V;
    float4*       ap = (float4*)agg       + (size_t)d * V;
#pragma unroll
    for (int v = sub; v < V; v += LPE) {
        float4 hv = hp[v];
        float mx = hv.x * norm, my = hv.y * norm, mz = hv.z * norm, mw = hv.w * norm;
        asm volatile("red.global.add.v4.f32 [%0], {%1, %2, %3, %4};"
                     :: "l"(ap + v), "f"(mx), "f"(my), "f"(mz), "f"(mw)
                     : "memory");
    }
}

// ---------------- launch ---------------------------------------------------
extern "C" void kernel_launch(void* const* d_in, const int* in_sizes, int n_in,
                              void* d_out, int out_size)
{
    const float* x   = (const float*)d_in[0];
    const int*   ei  = (const int*)  d_in[1];   // [2, E] int32, row-major
    const float* W1  = (const float*)d_in[2];
    const float* b1  = (const float*)d_in[3];
    const float* W2  = (const float*)d_in[4];
    const float* b2  = (const float*)d_in[5];
    const float* Wd1 = (const float*)d_in[6];
    const float* bd1 = (const float*)d_in[7];
    const float* Wd2 = (const float*)d_in[8];
    const float* bd2 = (const float*)d_in[9];
    float* out = (float*)d_out;

    const int* srcp = ei;
    const int* dstp = ei + ECNT;

    float *p_aggx, *p_h1r, *p_h2, *p_z, *p_d;
    cudaGetSymbolAddress((void**)&p_aggx, g_aggx);
    cudaGetSymbolAddress((void**)&p_h1r,  g_h1r);
    cudaGetSymbolAddress((void**)&p_h2,   g_h2);
    cudaGetSymbolAddress((void**)&p_z,    g_z);
    cudaGetSymbolAddress((void**)&p_d,    g_d);

    // --- degree + normalization
    k_deg_init <<<(NN   + 255) / 256, 256>>>();
    k_deg_count<<<(ECNT + 255) / 256, 256>>>(dstp);
    k_dinv     <<<(NN   + 255) / 256, 256>>>();

    const int MB = (NN + 127) / 128;   // 391 row-blocks

    // --- layer 1 (restructured): aggx = Dsym-scatter(x);  h1r = relu(aggx@W1 + b1)
    k_init_agg<128,false><<<(NN * 32 + 255) / 256, 256>>>(x, nullptr, p_aggx);
    k_scatter<128,32><<<(ECNT * 32) / 256, 256>>>(srcp, dstp, x, p_aggx);
    k_gemm<true,true><<<dim3(256/64, MB), 256>>>(p_aggx, W1, b1, p_h1r, NN, 256, 128);

    // --- layer 2: h2 = h1r @ W2 ; z = scatter(h2) + b2
    k_gemm<false,false><<<dim3(64/64, MB), 256>>>(p_h1r, W2, nullptr, p_h2, NN, 64, 256);
    k_init_agg<64,true><<<(NN * 16 + 255) / 256, 256>>>(p_h2, b2, p_z);
    k_scatter<64,16><<<(ECNT * 16) / 256, 256>>>(srcp, dstp, p_h2, p_z);

    // --- decoder: d = relu(z @ Wd1 + bd1) ; out = d @ Wd2 + bd2
    k_gemm<true,true ><<<dim3(256/64, MB), 256>>>(p_z, Wd1, bd1, p_d, NN, 256, 64);
    k_gemm<true,false><<<dim3(128/64, MB), 256>>>(p_d, Wd2, bd2, out, NN, 128, 256);
}